// round 4
// baseline (speedup 1.0000x reference)
#include <cuda_runtime.h>
#include <math.h>

#define FDIM 256
#define BMAX 1024
#define NMAX 1048576

typedef unsigned long long ull;

// ---------------- scratch (static device globals; no allocation) ----------------
__device__ __align__(128) float g_kq [BMAX * FDIM];
__device__ __align__(128) float g_vm [BMAX * FDIM];
__device__ __align__(128) float g_dot[NMAX];
__device__ __align__(128) float g_smax[BMAX];
__device__ __align__(128) float g_inv [BMAX];

__device__ __forceinline__ float actf(float x) {
    return x / (1.0f + expf(-1.702f * x));
}

__device__ __forceinline__ ull ffma2(ull a, ull b, ull c) {
    ull d;
    asm("fma.rn.f32x2 %0, %1, %2, %3;" : "=l"(d) : "l"(a), "l"(b), "l"(c));
    return d;
}
__device__ __forceinline__ float pairsum(ull v) {
    float2 f = *(float2*)&v;
    return f.x + f.y;
}
__device__ __forceinline__ ull dup2(float w) {
    ull d;
    asm("mov.b64 %0, {%1, %1};" : "=l"(d) : "f"(w));
    return d;
}

// ---------------- fused resMLP chain ----------------
// One block = 8 molecule rows through the WHOLE chain.
// blockIdx.y = 0: k branch (4 matrix layers, incl. trailing @Wq), 1: v branch (3 layers).
// Thread t owns output column c = t. A buffers in smem (broadcast reads),
// W streamed from global (L2-resident), FFMA2 packed over k-pairs.
__device__ __forceinline__ void gemm8(const float* __restrict__ W,
                                      const float* __restrict__ A,
                                      int c, float o[8]) {
    ull acc[8];
    #pragma unroll
    for (int r = 0; r < 8; r++) acc[r] = 0;
    const ulonglong2* __restrict__ w2 = (const ulonglong2*)(W + (size_t)c * FDIM);
    #pragma unroll 4
    for (int kk = 0; kk < 64; kk++) {       // 4 k per iter
        ulonglong2 w = w2[kk];
        #pragma unroll
        for (int r = 0; r < 8; r++) {
            ulonglong2 a = *(const ulonglong2*)(A + r * FDIM + kk * 4);
            acc[r] = ffma2(a.x, w.x, acc[r]);
            acc[r] = ffma2(a.y, w.y, acc[r]);
        }
    }
    #pragma unroll
    for (int r = 0; r < 8; r++) o[r] = pairsum(acc[r]);
}

__global__ __launch_bounds__(256, 1)
void fused_mlp_kernel(const float* __restrict__ E,
                      const float* __restrict__ Wkf, const float* __restrict__ bkf,
                      const float* __restrict__ Wvf,
                      const float* __restrict__ kW1, const float* __restrict__ kb1,
                      const float* __restrict__ kW2, const float* __restrict__ kb2,
                      const float* __restrict__ kWo, const float* __restrict__ kbo,
                      const float* __restrict__ vW1, const float* __restrict__ vW2,
                      const float* __restrict__ vWo, const float* __restrict__ Wq,
                      float* __restrict__ kq, float* __restrict__ vm,
                      int B) {
    __shared__ __align__(16) float bufA[8 * FDIM];
    __shared__ __align__(16) float bufB[8 * FDIM];
    __shared__ __align__(16) float kmT[FDIM * 8];   // km transposed [c][r]
    __shared__ float Es[8];

    int c = threadIdx.x;
    int isK = (blockIdx.y == 0);
    int row0 = blockIdx.x * 8;

    if (c < 8) Es[c] = (row0 + c < B) ? E[row0 + c] : 0.f;
    __syncthreads();

    // entry: h0 = E*wf + bf ; a0 = act(h0)
    float wf_c = isK ? Wkf[c] : Wvf[c];
    float bf_c = isK ? bkf[c] : 0.f;
    #pragma unroll
    for (int r = 0; r < 8; r++)
        bufA[r * FDIM + c] = actf(Es[r] * wf_c + bf_c);
    __syncthreads();

    float o[8];

    // L1: t1 = act(a0 @ W1^T + b1)
    gemm8(isK ? kW1 : vW1, bufA, c, o);
    {
        float b1 = isK ? kb1[c] : 0.f;
        #pragma unroll
        for (int r = 0; r < 8; r++)
            bufB[r * FDIM + c] = actf(o[r] + b1);
    }
    __syncthreads();

    // L2: ar = act(h0 + t1 @ W2^T + b2)
    gemm8(isK ? kW2 : vW2, bufB, c, o);
    {
        float b2 = isK ? kb2[c] : 0.f;
        #pragma unroll
        for (int r = 0; r < 8; r++)
            bufA[r * FDIM + c] = actf(o[r] + b2 + (Es[r] * wf_c + bf_c));
    }
    __syncthreads();

    // L3: mol = ar @ Wo^T + bo
    gemm8(isK ? kWo : vWo, bufA, c, o);

    if (!isK) {
        #pragma unroll
        for (int r = 0; r < 8; r++)
            if (row0 + r < B) vm[(size_t)(row0 + r) * FDIM + c] = o[r];
        return;
    }

    {
        float bo = kbo[c];
        #pragma unroll
        for (int r = 0; r < 8; r++)
            kmT[c * 8 + r] = o[r] + bo;
    }
    __syncthreads();

    // L4: kq[r][f] = sum_c km[r][c] * Wq[c][f]   (f = this thread's c)
    // Wq column reads are lane-coalesced; rows packed in FFMA2 pairs.
    ull acc[4] = {0, 0, 0, 0};
    const float* __restrict__ wcol = Wq + c;
    #pragma unroll 4
    for (int cc = 0; cc < FDIM; cc++) {
        ulonglong2 a01 = *(const ulonglong2*)(kmT + cc * 8);      // rows 0..3
        ulonglong2 a23 = *(const ulonglong2*)(kmT + cc * 8 + 4);  // rows 4..7
        ull wd = dup2(__ldg(wcol + (size_t)cc * FDIM));
        acc[0] = ffma2(a01.x, wd, acc[0]);
        acc[1] = ffma2(a01.y, wd, acc[1]);
        acc[2] = ffma2(a23.x, wd, acc[2]);
        acc[3] = ffma2(a23.y, wd, acc[3]);
    }
    #pragma unroll
    for (int p = 0; p < 4; p++) {
        float2 f2 = *(float2*)&acc[p];
        int r = 2 * p;
        if (row0 + r < B)     kq[(size_t)(row0 + r) * FDIM + c]     = f2.x;
        if (row0 + r + 1 < B) kq[(size_t)(row0 + r + 1) * FDIM + c] = f2.y;
    }
}

// ---------------- seg helpers (int32 buffer that may really be int64) ----------------
__device__ __forceinline__ int seg_is64(const int* __restrict__ s, int N) {
    // sorted, max = B-1 > 0. int64 LE => int32 view at N-1 is a high word = 0.
    return s[N - 1] == 0;
}

// ---------------- dot pass: dot[i] = x[i,:] . kq[seg[i],:] ----------------
__global__ void dot_kernel(const float4* __restrict__ x,
                           const int* __restrict__ seg32,
                           const float* __restrict__ kq,
                           float* __restrict__ dotv,
                           int N) {
    int gw   = (blockIdx.x * blockDim.x + threadIdx.x) >> 5;
    int lane = threadIdx.x & 31;
    if (gw >= N) return;
    int is64 = seg_is64(seg32, N);
    int b = seg32[is64 ? 2 * gw : gw];
    const float4* xr = x + (size_t)gw * 64;
    const float4* kr = (const float4*)kq + (size_t)b * 64;

    float4 a0 = xr[lane];
    float4 k0 = kr[lane];
    float4 a1 = xr[lane + 32];
    float4 k1 = kr[lane + 32];
    float s = a0.x * k0.x + a0.y * k0.y + a0.z * k0.z + a0.w * k0.w
            + a1.x * k1.x + a1.y * k1.y + a1.z * k1.z + a1.w * k1.w;
    #pragma unroll
    for (int o = 16; o; o >>= 1) s += __shfl_xor_sync(0xffffffffu, s, o);
    if (lane == 0) dotv[gw] = s;
}

// ---------------- segment reduce (deterministic, per-segment block) ----------------
__device__ __forceinline__ int lowerb(const int* __restrict__ s, int n, int v, int st) {
    int lo = 0, hi = n;
    while (lo < hi) {
        int mid = (lo + hi) >> 1;
        if (s[mid * st] < v) lo = mid + 1; else hi = mid;
    }
    return lo;
}

__global__ void segreduce_kernel(const int* __restrict__ seg32,
                                 const float* __restrict__ dotv,
                                 float* __restrict__ smax,
                                 float* __restrict__ invnorm,
                                 int N, float scale) {
    __shared__ float red[256];
    __shared__ int sse[2];
    int b = blockIdx.x;
    int t = threadIdx.x;
    if (t == 0) {
        int st = seg_is64(seg32, N) ? 2 : 1;
        sse[0] = lowerb(seg32, N, b, st);
        sse[1] = lowerb(seg32, N, b + 1, st);
    }
    __syncthreads();
    int start = sse[0], end = sse[1];

    float m = -3.4e38f;
    for (int i = start + t; i < end; i += 256) m = fmaxf(m, dotv[i]);
    red[t] = m;
    __syncthreads();
    #pragma unroll
    for (int s = 128; s; s >>= 1) {
        if (t < s) red[t] = fmaxf(red[t], red[t + s]);
        __syncthreads();
    }
    float mx = red[0];
    __syncthreads();

    float ss = 0.f;
    for (int i = start + t; i < end; i += 256) ss += expf((dotv[i] - mx) * scale);
    red[t] = ss;
    __syncthreads();
    #pragma unroll
    for (int s = 128; s; s >>= 1) {
        if (t < s) red[t] += red[t + s];
        __syncthreads();
    }
    if (t == 0) {
        smax[b] = mx;
        invnorm[b] = 1.f / (red[0] + 1e-8f);
    }
}

// ---------------- output pass ----------------
__global__ void out_kernel(const float* __restrict__ dotv,
                           const int* __restrict__ seg32,
                           const float* __restrict__ vm,
                           const float* __restrict__ smax,
                           const float* __restrict__ invnorm,
                           float4* __restrict__ out,
                           int N, float scale) {
    int gw   = (blockIdx.x * blockDim.x + threadIdx.x) >> 5;
    int lane = threadIdx.x & 31;
    if (gw >= N) return;
    int is64 = seg_is64(seg32, N);
    int b = seg32[is64 ? 2 * gw : gw];
    float coef = expf((dotv[gw] - smax[b]) * scale) * invnorm[b];
    const float4* vr = (const float4*)vm + (size_t)b * 64;
    float4* orow = out + (size_t)gw * 64;

    float4 v0 = vr[lane];
    v0.x *= coef; v0.y *= coef; v0.z *= coef; v0.w *= coef;
    orow[lane] = v0;
    float4 v1 = vr[lane + 32];
    v1.x *= coef; v1.y *= coef; v1.z *= coef; v1.w *= coef;
    orow[lane + 32] = v1;
}

// ---------------- launcher ----------------
extern "C" void kernel_launch(void* const* d_in, const int* in_sizes, int n_in,
                              void* d_out, int out_size) {
    int sh = (n_in >= 17) ? 0 : 1;
    const float* x    = (const float*)d_in[0];
    const float* E    = (const float*)d_in[1];
    const int*   seg  = (const int*)  d_in[3 - sh];
    const float* Wq   = (const float*)d_in[4 - sh];
    const float* Wkf  = (const float*)d_in[5 - sh];
    const float* bkf  = (const float*)d_in[6 - sh];
    const float* Wvf  = (const float*)d_in[7 - sh];
    const float* kW1  = (const float*)d_in[8 - sh];
    const float* kb1  = (const float*)d_in[9 - sh];
    const float* kW2  = (const float*)d_in[10 - sh];
    const float* kb2  = (const float*)d_in[11 - sh];
    const float* kWo  = (const float*)d_in[12 - sh];
    const float* kbo  = (const float*)d_in[13 - sh];
    const float* vW1  = (const float*)d_in[14 - sh];
    const float* vW2  = (const float*)d_in[15 - sh];
    const float* vWo  = (const float*)d_in[16 - sh];

    int B = in_sizes[1];
    int N = in_sizes[3 - sh];
    float scale = 1.f / 16.f;   // 1/sqrt(256)

    float *kq, *vm, *dotv, *smax, *inv;
    cudaGetSymbolAddress((void**)&kq,  g_kq);
    cudaGetSymbolAddress((void**)&vm,  g_vm);
    cudaGetSymbolAddress((void**)&dotv, g_dot);
    cudaGetSymbolAddress((void**)&smax, g_smax);
    cudaGetSymbolAddress((void**)&inv,  g_inv);

    // 1) whole resMLP chain (both branches) in one launch
    dim3 mgrid((B + 7) / 8, 2);
    fused_mlp_kernel<<<mgrid, 256>>>(E, Wkf, bkf, Wvf,
                                     kW1, kb1, kW2, kb2, kWo, kbo,
                                     vW1, vW2, vWo, Wq,
                                     kq, vm, B);

    // 2) streaming passes
    int nwb = (N * 32 + 255) / 256;
    dot_kernel<<<nwb, 256>>>((const float4*)x, seg, kq, dotv, N);
    segreduce_kernel<<<B, 256>>>(seg, dotv, smax, inv, N, scale);
    out_kernel<<<nwb, 256>>>(dotv, seg, vm, smax, inv, (float4*)d_out, N, scale);
}

// round 5
// speedup vs baseline: 1.1365x; 1.1365x over previous
#include <cuda_runtime.h>
#include <math.h>

#define FDIM 256
#define BMAX 1024
#define NMAX 1048576
#define SW_STRIDE 66      // floats per W row in smem (64 data + 2 pad)
#define CHUNK_K 64

typedef unsigned long long ull;

// ---------------- scratch (static device globals; no allocation) ----------------
__device__ __align__(128) float g_kq [BMAX * FDIM];
__device__ __align__(128) float g_vm [BMAX * FDIM];
__device__ __align__(128) float g_dot[NMAX];
__device__ __align__(128) float g_smax[BMAX];
__device__ __align__(128) float g_inv [BMAX];

__device__ __forceinline__ float actf(float x) {
    return x / (1.0f + expf(-1.702f * x));
}
__device__ __forceinline__ ull ffma2(ull a, ull b, ull c) {
    ull d;
    asm("fma.rn.f32x2 %0, %1, %2, %3;" : "=l"(d) : "l"(a), "l"(b), "l"(c));
    return d;
}
__device__ __forceinline__ float pairsum(ull v) {
    float2 f = *(float2*)&v;
    return f.x + f.y;
}
__device__ __forceinline__ ull dup2(float w) {
    ull d;
    asm("mov.b64 %0, {%1, %1};" : "=l"(d) : "f"(w));
    return d;
}
__device__ __forceinline__ float dot4(float4 a, float4 b) {
    return a.x * b.x + a.y * b.y + a.z * b.z + a.w * b.w;
}

// ---------------- fused resMLP chain ----------------
// Block = 8 molecule rows through the whole chain. blockIdx.y: 0=k branch
// (incl. trailing @Wq), 1=v branch. Thread t owns output column c=t.
// W is staged per 64-k chunk into smem with COALESCED warp-cooperative loads.

// stage W[0..255][k0..k0+63] -> sW (layout [row][kchunk], stride SW_STRIDE)
__device__ __forceinline__ void stageW(const float* __restrict__ W, float* sW,
                                       int k0, int t) {
    int lane = t & 31, w = t >> 5;
    int sub = lane >> 4;          // 0/1: row within pair
    int f4  = lane & 15;          // float4 index along k
    #pragma unroll
    for (int i = 0; i < 16; i++) {
        int row = i * 16 + w * 2 + sub;
        float4 v = ((const float4*)(W + (size_t)row * FDIM + k0))[f4];
        float* d = sW + row * SW_STRIDE + f4 * 4;
        *(float2*)(d)     = make_float2(v.x, v.y);
        *(float2*)(d + 2) = make_float2(v.z, v.w);
    }
}

// accumulate one chunk: acc[r] (f32x2 over k-pairs) += A[r][k0..] * sW[c][..]
__device__ __forceinline__ void gemm_chunk(const float* sW, const float* A,
                                           int c, int k0, ull acc[8]) {
    const float* wr = sW + c * SW_STRIDE;
    #pragma unroll 4
    for (int kk = 0; kk < CHUNK_K / 4; kk++) {     // 4 k (= 2 pairs) per iter
        ull w0 = *(const ull*)(wr + kk * 4);
        ull w1 = *(const ull*)(wr + kk * 4 + 2);
        #pragma unroll
        for (int r = 0; r < 8; r++) {
            ulonglong2 a = *(const ulonglong2*)(A + r * FDIM + k0 + kk * 4);
            acc[r] = ffma2(a.x, w0, acc[r]);
            acc[r] = ffma2(a.y, w1, acc[r]);
        }
    }
}

// one full 256x256 layer: o[r] = A[r,:] . W[c,:]
__device__ __forceinline__ void layer(const float* __restrict__ W,
                                      const float* A, float* sW,
                                      int c, int t, float o[8]) {
    ull acc[8] = {0, 0, 0, 0, 0, 0, 0, 0};
    #pragma unroll
    for (int ch = 0; ch < 4; ch++) {
        __syncthreads();                 // prior sW readers / A writers done
        stageW(W, sW, ch * CHUNK_K, t);
        __syncthreads();
        gemm_chunk(sW, A, c, ch * CHUNK_K, acc);
    }
    #pragma unroll
    for (int r = 0; r < 8; r++) o[r] = pairsum(acc[r]);
}

__global__ __launch_bounds__(256, 1)
void fused_mlp_kernel(const float* __restrict__ E,
                      const float* __restrict__ Wkf, const float* __restrict__ bkf,
                      const float* __restrict__ Wvf,
                      const float* __restrict__ kW1, const float* __restrict__ kb1,
                      const float* __restrict__ kW2, const float* __restrict__ kb2,
                      const float* __restrict__ kWo, const float* __restrict__ kbo,
                      const float* __restrict__ vW1, const float* __restrict__ vW2,
                      const float* __restrict__ vWo, const float* __restrict__ Wq,
                      float* __restrict__ kq, float* __restrict__ vm,
                      int B) {
    extern __shared__ __align__(16) float smdyn[];
    float* sW   = smdyn;                          // 256 * 66
    float* bufA = smdyn + 256 * SW_STRIDE;        // 8 * 256
    float* bufB = bufA + 8 * FDIM;                // 8 * 256 (aliased as kmT)
    __shared__ float Es[8];

    int c = threadIdx.x;
    int isK = (blockIdx.y == 0);
    int row0 = blockIdx.x * 8;

    if (c < 8) Es[c] = (row0 + c < B) ? E[row0 + c] : 0.f;
    __syncthreads();

    // entry: h0 = E*wf + bf ; a0 = act(h0)
    float wf_c = isK ? Wkf[c] : Wvf[c];
    float bf_c = isK ? bkf[c] : 0.f;
    #pragma unroll
    for (int r = 0; r < 8; r++)
        bufA[r * FDIM + c] = actf(Es[r] * wf_c + bf_c);

    float o[8];

    // L1: t1 = act(a0 @ W1^T + b1)
    layer(isK ? kW1 : vW1, bufA, sW, c, threadIdx.x, o);
    {
        float b1 = isK ? kb1[c] : 0.f;
        #pragma unroll
        for (int r = 0; r < 8; r++)
            bufB[r * FDIM + c] = actf(o[r] + b1);
    }

    // L2: ar = act(h0 + t1 @ W2^T + b2)
    layer(isK ? kW2 : vW2, bufB, sW, c, threadIdx.x, o);
    {
        float b2 = isK ? kb2[c] : 0.f;
        #pragma unroll
        for (int r = 0; r < 8; r++)
            bufA[r * FDIM + c] = actf(o[r] + b2 + (Es[r] * wf_c + bf_c));
    }

    // L3: mol = ar @ Wo^T + bo
    layer(isK ? kWo : vWo, bufA, sW, c, threadIdx.x, o);

    if (!isK) {
        #pragma unroll
        for (int r = 0; r < 8; r++)
            if (row0 + r < B) vm[(size_t)(row0 + r) * FDIM + c] = o[r];
        return;
    }

    // kmT[c][r] = km (transposed), reusing bufB
    float* kmT = bufB;
    {
        float bo = kbo[c];
        #pragma unroll
        for (int r = 0; r < 8; r++)
            kmT[c * 8 + r] = o[r] + bo;
    }
    __syncthreads();

    // L4: kq[r][f] = sum_cc km[r][cc] * Wq[cc][f]; Wq column reads coalesced
    ull acc[4] = {0, 0, 0, 0};
    const float* __restrict__ wcol = Wq + c;
    #pragma unroll 4
    for (int cc = 0; cc < FDIM; cc++) {
        ulonglong2 a01 = *(const ulonglong2*)(kmT + cc * 8);
        ulonglong2 a23 = *(const ulonglong2*)(kmT + cc * 8 + 4);
        ull wd = dup2(__ldg(wcol + (size_t)cc * FDIM));
        acc[0] = ffma2(a01.x, wd, acc[0]);
        acc[1] = ffma2(a01.y, wd, acc[1]);
        acc[2] = ffma2(a23.x, wd, acc[2]);
        acc[3] = ffma2(a23.y, wd, acc[3]);
    }
    #pragma unroll
    for (int p = 0; p < 4; p++) {
        float2 f2 = *(float2*)&acc[p];
        int r = 2 * p;
        if (row0 + r < B)     kq[(size_t)(row0 + r) * FDIM + c]     = f2.x;
        if (row0 + r + 1 < B) kq[(size_t)(row0 + r + 1) * FDIM + c] = f2.y;
    }
}

// ---------------- seg helpers (int32 buffer that may really be int64) ----------------
__device__ __forceinline__ int seg_is64(const int* __restrict__ s, int N) {
    return s[N - 1] == 0;   // sorted, max=B-1>0; int64 LE high word at N-1 is 0
}

// ---------------- dot pass: 2 rows per warp, front-batched loads ----------------
__global__ void dot_kernel(const float4* __restrict__ x,
                           const int* __restrict__ seg32,
                           const float* __restrict__ kq,
                           float* __restrict__ dotv,
                           int N) {
    int gw   = (blockIdx.x * blockDim.x + threadIdx.x) >> 5;
    int lane = threadIdx.x & 31;
    int r0 = gw * 2;
    if (r0 >= N) return;
    int st = seg_is64(seg32, N) ? 2 : 1;
    bool two = (r0 + 1 < N);
    int b0 = seg32[(size_t)r0 * st];
    int b1 = two ? seg32[(size_t)(r0 + 1) * st] : b0;
    const float4* x0 = x + (size_t)r0 * 64;
    const float4* x1 = x + (size_t)(two ? r0 + 1 : r0) * 64;
    const float4* k0 = (const float4*)kq + (size_t)b0 * 64;
    const float4* k1 = (const float4*)kq + (size_t)b1 * 64;

    float4 a0 = x0[lane], a1 = x0[lane + 32];
    float4 a2 = x1[lane], a3 = x1[lane + 32];
    float4 c0 = k0[lane], c1 = k0[lane + 32];
    float4 c2 = k1[lane], c3 = k1[lane + 32];

    float s0 = dot4(a0, c0) + dot4(a1, c1);
    float s1 = dot4(a2, c2) + dot4(a3, c3);
    #pragma unroll
    for (int o = 16; o; o >>= 1) {
        s0 += __shfl_xor_sync(0xffffffffu, s0, o);
        s1 += __shfl_xor_sync(0xffffffffu, s1, o);
    }
    if (lane == 0) {
        dotv[r0] = s0;
        if (two) dotv[r0 + 1] = s1;
    }
}

// ---------------- segment reduce (deterministic, per-segment block) ----------------
__device__ __forceinline__ int lowerb(const int* __restrict__ s, int n, int v, int st) {
    int lo = 0, hi = n;
    while (lo < hi) {
        int mid = (lo + hi) >> 1;
        if (s[(size_t)mid * st] < v) lo = mid + 1; else hi = mid;
    }
    return lo;
}

__global__ void segreduce_kernel(const int* __restrict__ seg32,
                                 const float* __restrict__ dotv,
                                 float* __restrict__ smax,
                                 float* __restrict__ invnorm,
                                 int N, float scale) {
    __shared__ float red[256];
    __shared__ int sse[2];
    int b = blockIdx.x;
    int t = threadIdx.x;
    if (t == 0) {
        int st = seg_is64(seg32, N) ? 2 : 1;
        sse[0] = lowerb(seg32, N, b, st);
        sse[1] = lowerb(seg32, N, b + 1, st);
    }
    __syncthreads();
    int start = sse[0], end = sse[1];

    float m = -3.4e38f;
    for (int i = start + t; i < end; i += 256) m = fmaxf(m, dotv[i]);
    red[t] = m;
    __syncthreads();
    #pragma unroll
    for (int s = 128; s; s >>= 1) {
        if (t < s) red[t] = fmaxf(red[t], red[t + s]);
        __syncthreads();
    }
    float mx = red[0];
    __syncthreads();

    float ss = 0.f;
    for (int i = start + t; i < end; i += 256) ss += expf((dotv[i] - mx) * scale);
    red[t] = ss;
    __syncthreads();
    #pragma unroll
    for (int s = 128; s; s >>= 1) {
        if (t < s) red[t] += red[t + s];
        __syncthreads();
    }
    if (t == 0) {
        smax[b] = mx;
        invnorm[b] = 1.f / (red[0] + 1e-8f);
    }
}

// ---------------- output pass: 32 rows per warp, vm register-cached ----------------
__global__ void out_kernel(const float* __restrict__ dotv,
                           const int* __restrict__ seg32,
                           const float* __restrict__ vm,
                           const float* __restrict__ smax,
                           const float* __restrict__ invnorm,
                           float4* __restrict__ out,
                           int N, float scale) {
    int gw   = (blockIdx.x * blockDim.x + threadIdx.x) >> 5;
    int lane = threadIdx.x & 31;
    int row0 = gw * 32;
    if (row0 >= N) return;
    int st = seg_is64(seg32, N) ? 2 : 1;

    // lane-parallel coefficient precompute for the 32 rows
    int myrow = row0 + lane;
    int bl = 0; float cl = 0.f;
    if (myrow < N) {
        bl = seg32[(size_t)myrow * st];
        cl = expf((dotv[myrow] - smax[bl]) * scale) * invnorm[bl];
    }

    int nrows = N - row0; if (nrows > 32) nrows = 32;
    int bcur = -1;
    float4 v0, v1;
    for (int r = 0; r < nrows; r++) {
        int b     = __shfl_sync(0xffffffffu, bl, r);
        float cf  = __shfl_sync(0xffffffffu, cl, r);
        if (b != bcur) {
            const float4* vr = (const float4*)vm + (size_t)b * 64;
            v0 = vr[lane];
            v1 = vr[lane + 32];
            bcur = b;
        }
        float4 o0 = make_float4(v0.x * cf, v0.y * cf, v0.z * cf, v0.w * cf);
        float4 o1 = make_float4(v1.x * cf, v1.y * cf, v1.z * cf, v1.w * cf);
        float4* orow = out + (size_t)(row0 + r) * 64;
        orow[lane]      = o0;
        orow[lane + 32] = o1;
    }
}

// ---------------- launcher ----------------
extern "C" void kernel_launch(void* const* d_in, const int* in_sizes, int n_in,
                              void* d_out, int out_size) {
    int sh = (n_in >= 17) ? 0 : 1;
    const float* x    = (const float*)d_in[0];
    const float* E    = (const float*)d_in[1];
    const int*   seg  = (const int*)  d_in[3 - sh];
    const float* Wq   = (const float*)d_in[4 - sh];
    const float* Wkf  = (const float*)d_in[5 - sh];
    const float* bkf  = (const float*)d_in[6 - sh];
    const float* Wvf  = (const float*)d_in[7 - sh];
    const float* kW1  = (const float*)d_in[8 - sh];
    const float* kb1  = (const float*)d_in[9 - sh];
    const float* kW2  = (const float*)d_in[10 - sh];
    const float* kb2  = (const float*)d_in[11 - sh];
    const float* kWo  = (const float*)d_in[12 - sh];
    const float* kbo  = (const float*)d_in[13 - sh];
    const float* vW1  = (const float*)d_in[14 - sh];
    const float* vW2  = (const float*)d_in[15 - sh];
    const float* vWo  = (const float*)d_in[16 - sh];

    int B = in_sizes[1];
    int N = in_sizes[3 - sh];
    float scale = 1.f / 16.f;   // 1/sqrt(256)

    float *kq, *vm, *dotv, *smax, *inv;
    cudaGetSymbolAddress((void**)&kq,  g_kq);
    cudaGetSymbolAddress((void**)&vm,  g_vm);
    cudaGetSymbolAddress((void**)&dotv, g_dot);
    cudaGetSymbolAddress((void**)&smax, g_smax);
    cudaGetSymbolAddress((void**)&inv,  g_inv);

    // 1) whole resMLP chain (both branches) in one launch
    const int MLP_SMEM = (256 * SW_STRIDE + 2 * 8 * FDIM) * (int)sizeof(float); // 83968
    cudaFuncSetAttribute(fused_mlp_kernel, cudaFuncAttributeMaxDynamicSharedMemorySize, MLP_SMEM);
    dim3 mgrid((B + 7) / 8, 2);
    fused_mlp_kernel<<<mgrid, 256, MLP_SMEM>>>(E, Wkf, bkf, Wvf,
                                               kW1, kb1, kW2, kb2, kWo, kbo,
                                               vW1, vW2, vWo, Wq,
                                               kq, vm, B);

    // 2) dot pass: 2 rows per warp
    {
        int warps = (N + 1) / 2;
        int blocks = (warps * 32 + 255) / 256;
        dot_kernel<<<blocks, 256>>>((const float4*)x, seg, kq, dotv, N);
    }

    // 3) deterministic per-segment max + expsum
    segreduce_kernel<<<B, 256>>>(seg, dotv, smax, inv, N, scale);

    // 4) output pass: 32 rows per warp
    {
        int warps = (N + 31) / 32;
        int blocks = (warps * 32 + 255) / 256;
        out_kernel<<<blocks, 256>>>(dotv, seg, vm, smax, inv, (float4*)d_out, N, scale);
    }
}